// round 2
// baseline (speedup 1.0000x reference)
#include <cuda_runtime.h>
#include <cstdint>

// ============================================================
// BayesianDenseLayer: out = x @ (w_loc + softplus(w_std)*eps_w) + b
// x: [8192,4096] f32, W: [4096,4096] f32, out: [8192,4096] f32
//
// Target is base sm_100 (no 'a' suffix -> no tcgen05). Use the
// classic sm_80 path: cp.async 4-stage pipeline + ldmatrix +
// mma.sync.m16n8k8.tf32. Prep kernels pre-round both operands to
// tf32 (RNA) and transpose W to K-major so both operands are TN.
// ============================================================

#define DIN   4096
#define DOUT  4096
#define BATCH 8192

__device__ float g_Wt[(size_t)DIN * DOUT];   // [DOUT][DIN], K contiguous, tf32-rounded
__device__ float g_Ar[(size_t)BATCH * DIN];  // x rounded to tf32
__device__ float g_b[DOUT];

// ---------------- helpers ----------------

__device__ __forceinline__ uint32_t smem_u32(const void* p) {
    uint32_t a;
    asm("{ .reg .u64 t; cvta.to.shared.u64 t, %1; cvt.u32.u64 %0, t; }" : "=r"(a) : "l"(p));
    return a;
}

__device__ __forceinline__ float tf32_rna(float v) {
    uint32_t u;
    asm("cvt.rna.tf32.f32 %0, %1;" : "=r"(u) : "f"(v));
    return __uint_as_float(u);
}

__device__ __forceinline__ float softplus_f(float x) {
    return fmaxf(x, 0.0f) + log1pf(expf(-fabsf(x)));
}

__device__ __forceinline__ void cp_async16(uint32_t dst, const void* src) {
    asm volatile("cp.async.cg.shared.global [%0], [%1], 16;" :: "r"(dst), "l"(src) : "memory");
}
__device__ __forceinline__ void cp_commit() {
    asm volatile("cp.async.commit_group;" ::: "memory");
}
__device__ __forceinline__ void cp_wait2() {
    asm volatile("cp.async.wait_group 2;" ::: "memory");
}

__device__ __forceinline__ void ldsm_x4(uint32_t* r, uint32_t addr) {
    asm volatile("ldmatrix.sync.aligned.m8n8.x4.shared.b16 {%0,%1,%2,%3}, [%4];"
                 : "=r"(r[0]), "=r"(r[1]), "=r"(r[2]), "=r"(r[3]) : "r"(addr));
}
__device__ __forceinline__ void ldsm_x2(uint32_t* r, uint32_t addr) {
    asm volatile("ldmatrix.sync.aligned.m8n8.x2.shared.b16 {%0,%1}, [%2];"
                 : "=r"(r[0]), "=r"(r[1]) : "r"(addr));
}

__device__ __forceinline__ void mma_tf32(float* c, const uint32_t* a, const uint32_t* b) {
    asm volatile(
        "mma.sync.aligned.m16n8k8.row.col.f32.tf32.tf32.f32 "
        "{%0,%1,%2,%3}, {%4,%5,%6,%7}, {%8,%9}, {%0,%1,%2,%3};"
        : "+f"(c[0]), "+f"(c[1]), "+f"(c[2]), "+f"(c[3])
        : "r"(a[0]), "r"(a[1]), "r"(a[2]), "r"(a[3]), "r"(b[0]), "r"(b[1]));
}

// ---------------- prep kernels ----------------

// g_Wt[n][k] = tf32_rna( w_loc[k][n] + softplus(w_std[k][n]) * eps_w[k][n] )
__global__ void prep_w_kernel(const float* __restrict__ wl,
                              const float* __restrict__ ws,
                              const float* __restrict__ ew) {
    __shared__ float tile[32][33];
    int n0 = blockIdx.x * 32, k0 = blockIdx.y * 32;
    int tx = threadIdx.x, ty = threadIdx.y;
    #pragma unroll
    for (int j = 0; j < 4; j++) {
        int k = k0 + ty + 8 * j;
        size_t idx = (size_t)k * DOUT + n0 + tx;
        float v = fmaf(softplus_f(ws[idx]), ew[idx], wl[idx]);
        tile[ty + 8 * j][tx] = tf32_rna(v);
    }
    __syncthreads();
    #pragma unroll
    for (int j = 0; j < 4; j++) {
        int n = n0 + ty + 8 * j;
        g_Wt[(size_t)n * DIN + k0 + tx] = tile[tx][ty + 8 * j];
    }
}

__global__ void prep_a_kernel(const float* __restrict__ x) {
    size_t i = (size_t)blockIdx.x * blockDim.x + threadIdx.x;
    size_t n4 = (size_t)BATCH * DIN / 4;
    const float4* src = (const float4*)x;
    float4* dst = (float4*)g_Ar;
    for (; i < n4; i += (size_t)gridDim.x * blockDim.x) {
        float4 v = src[i];
        v.x = tf32_rna(v.x); v.y = tf32_rna(v.y);
        v.z = tf32_rna(v.z); v.w = tf32_rna(v.w);
        dst[i] = v;
    }
}

__global__ void prep_b_kernel(const float* __restrict__ bl,
                              const float* __restrict__ bsd,
                              const float* __restrict__ eb) {
    int i = blockIdx.x * blockDim.x + threadIdx.x;
    if (i < DOUT) g_b[i] = fmaf(softplus_f(bsd[i]), eb[i], bl[i]);
}

// ---------------- GEMM ----------------

static constexpr int BM = 128, BN = 128, BK = 32;
static constexpr int STAGES = 4;
static constexpr int STAGE_BYTES = (BM + BN) * BK * 4;  // 32 KB
static constexpr int B_OFF = BM * BK * 4;               // 16 KB within stage
static constexpr int KITERS = DIN / BK;                 // 128

__global__ __launch_bounds__(256, 1)
void gemm_tf32_kernel(const float* __restrict__ A,   // g_Ar [BATCH][DIN]
                      const float* __restrict__ B,   // g_Wt [DOUT][DIN]
                      const float* __restrict__ bias,
                      float* __restrict__ out) {
    extern __shared__ __align__(128) char smem[];
    uint32_t sbase = smem_u32(smem);

    int tid  = threadIdx.x;
    int lane = tid & 31;
    int warp = tid >> 5;
    int wm = warp & 1;          // 2 warps along M
    int wn = warp >> 1;         // 4 warps along N
    int m0 = blockIdx.y * BM;
    int n0 = blockIdx.x * BN;

    // cp.async indices: 2048 chunks of 16B per stage (1024 A + 1024 B)
    // thread j-th chunk: cid = tid + j*256
    // A chunk: m = cid>>3, kc = cid&7 ; swizzled dst = m*128 + (kc*16 ^ ((m&7)<<4))
    const float* aSrcBase = A + (size_t)m0 * DIN;
    const float* bSrcBase = B + (size_t)n0 * DIN;

    auto copy_stage = [&](int s, int kt) {
        uint32_t st = sbase + s * STAGE_BYTES;
        int kbase = kt * BK;
        #pragma unroll
        for (int j = 0; j < 4; j++) {
            int cid = tid + j * 256;
            int m = cid >> 3, kc = cid & 7;
            uint32_t dst = st + m * 128 + ((kc * 16) ^ ((m & 7) << 4));
            cp_async16(dst, aSrcBase + (size_t)m * DIN + kbase + kc * 4);
        }
        #pragma unroll
        for (int j = 0; j < 4; j++) {
            int cid = tid + j * 256;
            int n = cid >> 3, kc = cid & 7;
            uint32_t dst = st + B_OFF + n * 128 + ((kc * 16) ^ ((n & 7) << 4));
            cp_async16(dst, bSrcBase + (size_t)n * DIN + kbase + kc * 4);
        }
    };

    // prologue: fill stages 0..2
    #pragma unroll
    for (int s = 0; s < STAGES - 1; s++) {
        copy_stage(s, s);
        cp_commit();
    }

    // per-thread ldmatrix bases
    int aRow = wm * 64 + (lane & 7) + ((lane >> 3) & 1) * 8;  // row within BM
    int aSel = ((lane >> 4) & 1) * 16;                         // byte sel (k 0-3 vs 4-7)
    uint32_t aXor = (uint32_t)(aRow & 7) << 4;
    int bRow = wn * 32 + (lane & 7);                           // row within BN
    int bSel = ((lane >> 3) & 1) * 16;
    uint32_t bXor = (uint32_t)(bRow & 7) << 4;

    float acc[4][4][4];
    #pragma unroll
    for (int mi = 0; mi < 4; mi++)
        #pragma unroll
        for (int nj = 0; nj < 4; nj++)
            #pragma unroll
            for (int c = 0; c < 4; c++) acc[mi][nj][c] = 0.0f;

    #pragma unroll 1
    for (int k = 0; k < KITERS; k++) {
        cp_wait2();
        __syncthreads();

        // prefetch stage k+3
        if (k + STAGES - 1 < KITERS) copy_stage((k + STAGES - 1) % STAGES, k + STAGES - 1);
        cp_commit();

        uint32_t sA = sbase + (k % STAGES) * STAGE_BYTES;
        uint32_t sB = sA + B_OFF;

        #pragma unroll
        for (int ks = 0; ks < 4; ks++) {
            uint32_t a[4][4], b[4][2];
            #pragma unroll
            for (int mi = 0; mi < 4; mi++) {
                uint32_t addr = sA + (uint32_t)(aRow + mi * 16) * 128
                              + (((uint32_t)(ks * 32 + aSel)) ^ aXor);
                ldsm_x4(a[mi], addr);
            }
            #pragma unroll
            for (int nj = 0; nj < 4; nj++) {
                uint32_t addr = sB + (uint32_t)(bRow + nj * 8) * 128
                              + (((uint32_t)(ks * 32 + bSel)) ^ bXor);
                ldsm_x2(b[nj], addr);
            }
            #pragma unroll
            for (int mi = 0; mi < 4; mi++)
                #pragma unroll
                for (int nj = 0; nj < 4; nj++)
                    mma_tf32(acc[mi][nj], a[mi], b[nj]);
        }
    }

    // -------- epilogue: add bias, store --------
    int g  = lane >> 2;
    int tg = lane & 3;
    #pragma unroll
    for (int nj = 0; nj < 4; nj++) {
        int col = n0 + wn * 32 + nj * 8 + tg * 2;
        float bx = bias[col], by = bias[col + 1];
        #pragma unroll
        for (int mi = 0; mi < 4; mi++) {
            int row = m0 + wm * 64 + mi * 16 + g;
            float2 v0 = make_float2(acc[mi][nj][0] + bx, acc[mi][nj][1] + by);
            float2 v1 = make_float2(acc[mi][nj][2] + bx, acc[mi][nj][3] + by);
            *reinterpret_cast<float2*>(out + (size_t)row * DOUT + col) = v0;
            *reinterpret_cast<float2*>(out + (size_t)(row + 8) * DOUT + col) = v1;
        }
    }
}

// ---------------- host launcher ----------------

extern "C" void kernel_launch(void* const* d_in, const int* in_sizes, int n_in,
                              void* d_out, int out_size) {
    const float* x   = (const float*)d_in[0];
    const float* wl  = (const float*)d_in[1];
    const float* ws  = (const float*)d_in[2];
    const float* bl  = (const float*)d_in[3];
    const float* bsd = (const float*)d_in[4];
    const float* ew  = (const float*)d_in[5];
    const float* eb  = (const float*)d_in[6];
    float* out = (float*)d_out;

    float *wt_ptr = nullptr, *ar_ptr = nullptr, *b_ptr = nullptr;
    cudaGetSymbolAddress((void**)&wt_ptr, g_Wt);
    cudaGetSymbolAddress((void**)&ar_ptr, g_Ar);
    cudaGetSymbolAddress((void**)&b_ptr,  g_b);

    prep_w_kernel<<<dim3(DOUT / 32, DIN / 32), dim3(32, 8)>>>(wl, ws, ew);
    prep_a_kernel<<<2048, 256>>>(x);
    prep_b_kernel<<<DOUT / 256, 256>>>(bl, bsd, eb);

    static bool attr_set = false;
    if (!attr_set) {
        cudaFuncSetAttribute(gemm_tf32_kernel,
                             cudaFuncAttributeMaxDynamicSharedMemorySize,
                             STAGES * STAGE_BYTES);
        attr_set = true;
    }

    // N tiles fastest: CTAs in a row share A tiles; full W (64 MB) lives in L2.
    gemm_tf32_kernel<<<dim3(DOUT / BN, BATCH / BM), 256, STAGES * STAGE_BYTES>>>(
        ar_ptr, wt_ptr, b_ptr, out);
}

// round 3
// speedup vs baseline: 1.1336x; 1.1336x over previous
#include <cuda_runtime.h>
#include <cstdint>

// ============================================================
// BayesianDenseLayer: out = x @ (w_loc + softplus(w_std)*eps_w) + b
// x: [8192,4096] f32, W: [4096,4096] f32, out: [8192,4096] f32
//
// Base sm_100 target (no tcgen05). cp.async 4-stage pipeline +
// ldmatrix + mma.sync.m16n8k8.tf32, both operands pre-rounded
// (RNA) and TN layout (W transposed to K-major).
// R3 change: CTA tile 128x256, warp tile 64x64, B via ldsm_x4.
// Tensor:smem cycle ratio goes 1:1 -> 1:0.69.
// ============================================================

#define DIN   4096
#define DOUT  4096
#define BATCH 8192

__device__ float g_Wt[(size_t)DIN * DOUT];   // [DOUT][DIN], K contiguous, tf32-rounded
__device__ float g_Ar[(size_t)BATCH * DIN];  // x rounded to tf32
__device__ float g_b[DOUT];

// ---------------- helpers ----------------

__device__ __forceinline__ uint32_t smem_u32(const void* p) {
    uint32_t a;
    asm("{ .reg .u64 t; cvta.to.shared.u64 t, %1; cvt.u32.u64 %0, t; }" : "=r"(a) : "l"(p));
    return a;
}

__device__ __forceinline__ float tf32_rna(float v) {
    uint32_t u;
    asm("cvt.rna.tf32.f32 %0, %1;" : "=r"(u) : "f"(v));
    return __uint_as_float(u);
}

__device__ __forceinline__ float softplus_f(float x) {
    return fmaxf(x, 0.0f) + log1pf(expf(-fabsf(x)));
}

__device__ __forceinline__ void cp_async16(uint32_t dst, const void* src) {
    asm volatile("cp.async.cg.shared.global [%0], [%1], 16;" :: "r"(dst), "l"(src) : "memory");
}
__device__ __forceinline__ void cp_commit() {
    asm volatile("cp.async.commit_group;" ::: "memory");
}
__device__ __forceinline__ void cp_wait2() {
    asm volatile("cp.async.wait_group 2;" ::: "memory");
}

__device__ __forceinline__ void ldsm_x4(uint32_t* r, uint32_t addr) {
    asm volatile("ldmatrix.sync.aligned.m8n8.x4.shared.b16 {%0,%1,%2,%3}, [%4];"
                 : "=r"(r[0]), "=r"(r[1]), "=r"(r[2]), "=r"(r[3]) : "r"(addr));
}

__device__ __forceinline__ void mma_tf32(float* c, const uint32_t* a, const uint32_t* b) {
    asm volatile(
        "mma.sync.aligned.m16n8k8.row.col.f32.tf32.tf32.f32 "
        "{%0,%1,%2,%3}, {%4,%5,%6,%7}, {%8,%9}, {%0,%1,%2,%3};"
        : "+f"(c[0]), "+f"(c[1]), "+f"(c[2]), "+f"(c[3])
        : "r"(a[0]), "r"(a[1]), "r"(a[2]), "r"(a[3]), "r"(b[0]), "r"(b[1]));
}

// ---------------- prep kernels ----------------

__global__ void prep_w_kernel(const float* __restrict__ wl,
                              const float* __restrict__ ws,
                              const float* __restrict__ ew) {
    __shared__ float tile[32][33];
    int n0 = blockIdx.x * 32, k0 = blockIdx.y * 32;
    int tx = threadIdx.x, ty = threadIdx.y;
    #pragma unroll
    for (int j = 0; j < 4; j++) {
        int k = k0 + ty + 8 * j;
        size_t idx = (size_t)k * DOUT + n0 + tx;
        float v = fmaf(softplus_f(ws[idx]), ew[idx], wl[idx]);
        tile[ty + 8 * j][tx] = tf32_rna(v);
    }
    __syncthreads();
    #pragma unroll
    for (int j = 0; j < 4; j++) {
        int n = n0 + ty + 8 * j;
        g_Wt[(size_t)n * DIN + k0 + tx] = tile[tx][ty + 8 * j];
    }
}

__global__ void prep_a_kernel(const float* __restrict__ x) {
    size_t i = (size_t)blockIdx.x * blockDim.x + threadIdx.x;
    size_t n4 = (size_t)BATCH * DIN / 4;
    const float4* src = (const float4*)x;
    float4* dst = (float4*)g_Ar;
    for (; i < n4; i += (size_t)gridDim.x * blockDim.x) {
        float4 v = src[i];
        v.x = tf32_rna(v.x); v.y = tf32_rna(v.y);
        v.z = tf32_rna(v.z); v.w = tf32_rna(v.w);
        dst[i] = v;
    }
}

__global__ void prep_b_kernel(const float* __restrict__ bl,
                              const float* __restrict__ bsd,
                              const float* __restrict__ eb) {
    int i = blockIdx.x * blockDim.x + threadIdx.x;
    if (i < DOUT) g_b[i] = fmaf(softplus_f(bsd[i]), eb[i], bl[i]);
}

// ---------------- GEMM ----------------

static constexpr int BM = 128, BN = 256, BK = 32;
static constexpr int STAGES = 4;
static constexpr int STAGE_BYTES = (BM + BN) * BK * 4;  // 48 KB
static constexpr int B_OFF = BM * BK * 4;               // 16 KB within stage
static constexpr int KITERS = DIN / BK;                 // 128

__global__ __launch_bounds__(256, 1)
void gemm_tf32_kernel(const float* __restrict__ A,   // g_Ar [BATCH][DIN]
                      const float* __restrict__ B,   // g_Wt [DOUT][DIN]
                      const float* __restrict__ bias,
                      float* __restrict__ out) {
    extern __shared__ __align__(128) char smem[];
    uint32_t sbase = smem_u32(smem);

    int tid  = threadIdx.x;
    int lane = tid & 31;
    int warp = tid >> 5;
    int wm = warp & 1;          // 2 warps along M (64 each)
    int wn = warp >> 1;         // 4 warps along N (64 each)
    int m0 = blockIdx.y * BM;
    int n0 = blockIdx.x * BN;

    const float* aSrcBase = A + (size_t)m0 * DIN;
    const float* bSrcBase = B + (size_t)n0 * DIN;

    // cp.async: A = 1024 16B chunks, B = 2048 chunks per stage
    auto copy_stage = [&](int s, int kt) {
        uint32_t st = sbase + s * STAGE_BYTES;
        int kbase = kt * BK;
        #pragma unroll
        for (int j = 0; j < 4; j++) {
            int cid = tid + j * 256;
            int m = cid >> 3, kc = cid & 7;
            uint32_t dst = st + m * 128 + ((kc * 16) ^ ((m & 7) << 4));
            cp_async16(dst, aSrcBase + (size_t)m * DIN + kbase + kc * 4);
        }
        #pragma unroll
        for (int j = 0; j < 8; j++) {
            int cid = tid + j * 256;
            int n = cid >> 3, kc = cid & 7;
            uint32_t dst = st + B_OFF + n * 128 + ((kc * 16) ^ ((n & 7) << 4));
            cp_async16(dst, bSrcBase + (size_t)n * DIN + kbase + kc * 4);
        }
    };

    #pragma unroll
    for (int s = 0; s < STAGES - 1; s++) {
        copy_stage(s, s);
        cp_commit();
    }

    // ldmatrix per-thread bases (row-XOR swizzle: (row&7)<<4; all row offsets
    // below are multiples of 8, so xor depends only on lane&7)
    int aRow = wm * 64 + (lane & 7) + ((lane >> 3) & 1) * 8;   // rows 0-15 for lanes 0-15
    int aSel = ((lane >> 4) & 1) * 16;                          // lanes 16-31: hi 16B
    int bRow = wn * 64 + ((lane >> 4) & 1) * 8 + (lane & 7);    // x4: two stacked x2 frags
    int bSel = ((lane >> 3) & 1) * 16;
    uint32_t xorv = (uint32_t)(lane & 7) << 4;

    float acc[4][8][4];
    #pragma unroll
    for (int mi = 0; mi < 4; mi++)
        #pragma unroll
        for (int nj = 0; nj < 8; nj++)
            #pragma unroll
            for (int c = 0; c < 4; c++) acc[mi][nj][c] = 0.0f;

    #pragma unroll 1
    for (int k = 0; k < KITERS; k++) {
        cp_wait2();
        __syncthreads();

        if (k + STAGES - 1 < KITERS) copy_stage((k + STAGES - 1) % STAGES, k + STAGES - 1);
        cp_commit();

        uint32_t sA = sbase + (k % STAGES) * STAGE_BYTES;
        uint32_t sB = sA + B_OFF;

        #pragma unroll
        for (int ks = 0; ks < 4; ks++) {
            uint32_t a[4][4], b[4][4];   // b[njp]: regs 0,1 = nj=2*njp, regs 2,3 = nj=2*njp+1
            #pragma unroll
            for (int mi = 0; mi < 4; mi++) {
                uint32_t addr = sA + (uint32_t)(aRow + mi * 16) * 128
                              + (((uint32_t)(ks * 32 + aSel)) ^ xorv);
                ldsm_x4(a[mi], addr);
            }
            #pragma unroll
            for (int njp = 0; njp < 4; njp++) {
                uint32_t addr = sB + (uint32_t)(bRow + njp * 16) * 128
                              + (((uint32_t)(ks * 32 + bSel)) ^ xorv);
                ldsm_x4(b[njp], addr);
            }
            #pragma unroll
            for (int mi = 0; mi < 4; mi++)
                #pragma unroll
                for (int njp = 0; njp < 4; njp++) {
                    mma_tf32(acc[mi][2 * njp],     a[mi], &b[njp][0]);
                    mma_tf32(acc[mi][2 * njp + 1], a[mi], &b[njp][2]);
                }
        }
    }

    // -------- epilogue: add bias, store --------
    int g  = lane >> 2;
    int tg = lane & 3;
    #pragma unroll
    for (int nj = 0; nj < 8; nj++) {
        int col = n0 + wn * 64 + nj * 8 + tg * 2;
        float bx = bias[col], by = bias[col + 1];
        #pragma unroll
        for (int mi = 0; mi < 4; mi++) {
            int row = m0 + wm * 64 + mi * 16 + g;
            float2 v0 = make_float2(acc[mi][nj][0] + bx, acc[mi][nj][1] + by);
            float2 v1 = make_float2(acc[mi][nj][2] + bx, acc[mi][nj][3] + by);
            *reinterpret_cast<float2*>(out + (size_t)row * DOUT + col) = v0;
            *reinterpret_cast<float2*>(out + (size_t)(row + 8) * DOUT + col) = v1;
        }
    }
}

// ---------------- host launcher ----------------

extern "C" void kernel_launch(void* const* d_in, const int* in_sizes, int n_in,
                              void* d_out, int out_size) {
    const float* x   = (const float*)d_in[0];
    const float* wl  = (const float*)d_in[1];
    const float* ws  = (const float*)d_in[2];
    const float* bl  = (const float*)d_in[3];
    const float* bsd = (const float*)d_in[4];
    const float* ew  = (const float*)d_in[5];
    const float* eb  = (const float*)d_in[6];
    float* out = (float*)d_out;

    float *wt_ptr = nullptr, *ar_ptr = nullptr, *b_ptr = nullptr;
    cudaGetSymbolAddress((void**)&wt_ptr, g_Wt);
    cudaGetSymbolAddress((void**)&ar_ptr, g_Ar);
    cudaGetSymbolAddress((void**)&b_ptr,  g_b);

    prep_w_kernel<<<dim3(DOUT / 32, DIN / 32), dim3(32, 8)>>>(wl, ws, ew);
    prep_a_kernel<<<2048, 256>>>(x);
    prep_b_kernel<<<DOUT / 256, 256>>>(bl, bsd, eb);

    static bool attr_set = false;
    if (!attr_set) {
        cudaFuncSetAttribute(gemm_tf32_kernel,
                             cudaFuncAttributeMaxDynamicSharedMemorySize,
                             STAGES * STAGE_BYTES);
        attr_set = true;
    }

    // N tiles fastest: CTAs in a row share A panel; W (64 MB) stays in L2.
    gemm_tf32_kernel<<<dim3(DOUT / BN, BATCH / BM), 256, STAGES * STAGE_BYTES>>>(
        ar_ptr, wt_ptr, b_ptr, out);
}

// round 4
// speedup vs baseline: 2.1256x; 1.8752x over previous
#include <cuda_runtime.h>
#include <cuda_fp16.h>
#include <cstdint>

// ============================================================
// BayesianDenseLayer: out = x @ (w_loc + softplus(w_std)*eps_w) + b
// x: [8192,4096] f32, W: [4096,4096] f32, out: [8192,4096] f32
//
// Base sm_100 target (no tcgen05). R4: switch tensor path from
// tf32 m16n8k8 (~273 TF/s ceiling) to f16 m16n8k16 with f32
// accumulate (2x rate, SAME 10-bit mantissa -> same accuracy).
// cp.async 4-stage pipeline + ldmatrix, CTA 128x256, warp 64x64,
// BK=64 halves (128B rows, same XOR swizzle as tf32 version).
// ============================================================

#define DIN   4096
#define DOUT  4096
#define BATCH 8192

__device__ __half g_Wt[(size_t)DIN * DOUT];   // [DOUT][DIN], K contiguous, fp16
__device__ __half g_Ar[(size_t)BATCH * DIN];  // x in fp16
__device__ float  g_b[DOUT];

// ---------------- helpers ----------------

__device__ __forceinline__ uint32_t smem_u32(const void* p) {
    uint32_t a;
    asm("{ .reg .u64 t; cvta.to.shared.u64 t, %1; cvt.u32.u64 %0, t; }" : "=r"(a) : "l"(p));
    return a;
}

__device__ __forceinline__ float softplus_f(float x) {
    return fmaxf(x, 0.0f) + log1pf(expf(-fabsf(x)));
}

__device__ __forceinline__ void cp_async16(uint32_t dst, const void* src) {
    asm volatile("cp.async.cg.shared.global [%0], [%1], 16;" :: "r"(dst), "l"(src) : "memory");
}
__device__ __forceinline__ void cp_commit() {
    asm volatile("cp.async.commit_group;" ::: "memory");
}
__device__ __forceinline__ void cp_wait2() {
    asm volatile("cp.async.wait_group 2;" ::: "memory");
}

__device__ __forceinline__ void ldsm_x4(uint32_t* r, uint32_t addr) {
    asm volatile("ldmatrix.sync.aligned.m8n8.x4.shared.b16 {%0,%1,%2,%3}, [%4];"
                 : "=r"(r[0]), "=r"(r[1]), "=r"(r[2]), "=r"(r[3]) : "r"(addr));
}

// m16n8k16 f16 with f32 accumulate
__device__ __forceinline__ void mma_f16(float* c, const uint32_t* a, const uint32_t* b) {
    asm volatile(
        "mma.sync.aligned.m16n8k16.row.col.f32.f16.f16.f32 "
        "{%0,%1,%2,%3}, {%4,%5,%6,%7}, {%8,%9}, {%0,%1,%2,%3};"
        : "+f"(c[0]), "+f"(c[1]), "+f"(c[2]), "+f"(c[3])
        : "r"(a[0]), "r"(a[1]), "r"(a[2]), "r"(a[3]), "r"(b[0]), "r"(b[1]));
}

// ---------------- prep kernels ----------------

// g_Wt[n][k] = fp16( w_loc[k][n] + softplus(w_std[k][n]) * eps_w[k][n] )
__global__ void prep_w_kernel(const float* __restrict__ wl,
                              const float* __restrict__ ws,
                              const float* __restrict__ ew) {
    __shared__ __half tile[32][33];
    int n0 = blockIdx.x * 32, k0 = blockIdx.y * 32;
    int tx = threadIdx.x, ty = threadIdx.y;
    #pragma unroll
    for (int j = 0; j < 4; j++) {
        int k = k0 + ty + 8 * j;
        size_t idx = (size_t)k * DOUT + n0 + tx;
        float v = fmaf(softplus_f(ws[idx]), ew[idx], wl[idx]);
        tile[ty + 8 * j][tx] = __float2half_rn(v);
    }
    __syncthreads();
    #pragma unroll
    for (int j = 0; j < 4; j++) {
        int n = n0 + ty + 8 * j;
        g_Wt[(size_t)n * DIN + k0 + tx] = tile[tx][ty + 8 * j];
    }
}

__global__ void prep_a_kernel(const float* __restrict__ x) {
    size_t i = (size_t)blockIdx.x * blockDim.x + threadIdx.x;
    size_t n4 = (size_t)BATCH * DIN / 4;
    const float4* src = (const float4*)x;
    __half2* dst = (__half2*)g_Ar;
    for (; i < n4; i += (size_t)gridDim.x * blockDim.x) {
        float4 v = src[i];
        dst[2 * i]     = __floats2half2_rn(v.x, v.y);
        dst[2 * i + 1] = __floats2half2_rn(v.z, v.w);
    }
}

__global__ void prep_b_kernel(const float* __restrict__ bl,
                              const float* __restrict__ bsd,
                              const float* __restrict__ eb) {
    int i = blockIdx.x * blockDim.x + threadIdx.x;
    if (i < DOUT) g_b[i] = fmaf(softplus_f(bsd[i]), eb[i], bl[i]);
}

// ---------------- GEMM ----------------

static constexpr int BM = 128, BN = 256, BK = 64;       // BK in halves (128 B rows)
static constexpr int STAGES = 4;
static constexpr int STAGE_BYTES = (BM + BN) * BK * 2;  // 48 KB
static constexpr int B_OFF = BM * BK * 2;               // 16 KB within stage
static constexpr int KITERS = DIN / BK;                 // 64

__global__ __launch_bounds__(256, 1)
void gemm_f16_kernel(const __half* __restrict__ A,   // g_Ar [BATCH][DIN]
                     const __half* __restrict__ B,   // g_Wt [DOUT][DIN]
                     const float* __restrict__ bias,
                     float* __restrict__ out) {
    extern __shared__ __align__(128) char smem[];
    uint32_t sbase = smem_u32(smem);

    int tid  = threadIdx.x;
    int lane = tid & 31;
    int warp = tid >> 5;
    int wm = warp & 1;          // 2 warps along M (64 each)
    int wn = warp >> 1;         // 4 warps along N (64 each)
    int m0 = blockIdx.y * BM;
    int n0 = blockIdx.x * BN;

    const __half* aSrcBase = A + (size_t)m0 * DIN;
    const __half* bSrcBase = B + (size_t)n0 * DIN;

    // cp.async: A = 1024 16B chunks, B = 2048 chunks per stage (12/thread)
    auto copy_stage = [&](int s, int kt) {
        uint32_t st = sbase + s * STAGE_BYTES;
        int kbase = kt * BK;
        #pragma unroll
        for (int j = 0; j < 4; j++) {
            int cid = tid + j * 256;
            int m = cid >> 3, kc = cid & 7;
            uint32_t dst = st + m * 128 + ((kc * 16) ^ ((m & 7) << 4));
            cp_async16(dst, aSrcBase + (size_t)m * DIN + kbase + kc * 8);
        }
        #pragma unroll
        for (int j = 0; j < 8; j++) {
            int cid = tid + j * 256;
            int n = cid >> 3, kc = cid & 7;
            uint32_t dst = st + B_OFF + n * 128 + ((kc * 16) ^ ((n & 7) << 4));
            cp_async16(dst, bSrcBase + (size_t)n * DIN + kbase + kc * 8);
        }
    };

    #pragma unroll
    for (int s = 0; s < STAGES - 1; s++) {
        copy_stage(s, s);
        cp_commit();
    }

    // ldmatrix per-thread bases.
    // A (m16n8k16): lanes 0-7 rows 0-7 (k0-7), 8-15 rows 8-15, 16-31 same rows k8-15.
    int aRow = wm * 64 + (lane & 7) + ((lane >> 3) & 1) * 8;
    int aSel = ((lane >> 4) & 1) * 16;
    // B x4 = two n8k16 fragments: lanes 0-7 n0-7 k0-7, 8-15 n0-7 k8-15,
    //                              16-23 n8-15 k0-7, 24-31 n8-15 k8-15.
    int bRow = wn * 64 + ((lane >> 4) & 1) * 8 + (lane & 7);
    int bSel = ((lane >> 3) & 1) * 16;
    uint32_t xorv = (uint32_t)(lane & 7) << 4;

    float acc[4][8][4];
    #pragma unroll
    for (int mi = 0; mi < 4; mi++)
        #pragma unroll
        for (int nj = 0; nj < 8; nj++)
            #pragma unroll
            for (int c = 0; c < 4; c++) acc[mi][nj][c] = 0.0f;

    #pragma unroll 1
    for (int k = 0; k < KITERS; k++) {
        cp_wait2();
        __syncthreads();

        if (k + STAGES - 1 < KITERS) copy_stage((k + STAGES - 1) % STAGES, k + STAGES - 1);
        cp_commit();

        uint32_t sA = sbase + (k % STAGES) * STAGE_BYTES;
        uint32_t sB = sA + B_OFF;

        #pragma unroll
        for (int ks = 0; ks < 4; ks++) {   // 4 x K=16 per 128B stage row
            uint32_t a[4][4], b[4][4];
            #pragma unroll
            for (int mi = 0; mi < 4; mi++) {
                uint32_t addr = sA + (uint32_t)(aRow + mi * 16) * 128
                              + (((uint32_t)(ks * 32 + aSel)) ^ xorv);
                ldsm_x4(a[mi], addr);
            }
            #pragma unroll
            for (int njp = 0; njp < 4; njp++) {
                uint32_t addr = sB + (uint32_t)(bRow + njp * 16) * 128
                              + (((uint32_t)(ks * 32 + bSel)) ^ xorv);
                ldsm_x4(b[njp], addr);
            }
            #pragma unroll
            for (int mi = 0; mi < 4; mi++)
                #pragma unroll
                for (int njp = 0; njp < 4; njp++) {
                    mma_f16(acc[mi][2 * njp],     a[mi], &b[njp][0]);
                    mma_f16(acc[mi][2 * njp + 1], a[mi], &b[njp][2]);
                }
        }
    }

    // -------- epilogue: add bias, store --------
    int g  = lane >> 2;
    int tg = lane & 3;
    #pragma unroll
    for (int nj = 0; nj < 8; nj++) {
        int col = n0 + wn * 64 + nj * 8 + tg * 2;
        float bx = bias[col], by = bias[col + 1];
        #pragma unroll
        for (int mi = 0; mi < 4; mi++) {
            int row = m0 + wm * 64 + mi * 16 + g;
            float2 v0 = make_float2(acc[mi][nj][0] + bx, acc[mi][nj][1] + by);
            float2 v1 = make_float2(acc[mi][nj][2] + bx, acc[mi][nj][3] + by);
            *reinterpret_cast<float2*>(out + (size_t)row * DOUT + col) = v0;
            *reinterpret_cast<float2*>(out + (size_t)(row + 8) * DOUT + col) = v1;
        }
    }
}

// ---------------- host launcher ----------------

extern "C" void kernel_launch(void* const* d_in, const int* in_sizes, int n_in,
                              void* d_out, int out_size) {
    const float* x   = (const float*)d_in[0];
    const float* wl  = (const float*)d_in[1];
    const float* ws  = (const float*)d_in[2];
    const float* bl  = (const float*)d_in[3];
    const float* bsd = (const float*)d_in[4];
    const float* ew  = (const float*)d_in[5];
    const float* eb  = (const float*)d_in[6];
    float* out = (float*)d_out;

    __half *wt_ptr = nullptr, *ar_ptr = nullptr;
    float *b_ptr = nullptr;
    cudaGetSymbolAddress((void**)&wt_ptr, g_Wt);
    cudaGetSymbolAddress((void**)&ar_ptr, g_Ar);
    cudaGetSymbolAddress((void**)&b_ptr,  g_b);

    prep_w_kernel<<<dim3(DOUT / 32, DIN / 32), dim3(32, 8)>>>(wl, ws, ew);
    prep_a_kernel<<<2048, 256>>>(x);
    prep_b_kernel<<<DOUT / 256, 256>>>(bl, bsd, eb);

    static bool attr_set = false;
    if (!attr_set) {
        cudaFuncSetAttribute(gemm_f16_kernel,
                             cudaFuncAttributeMaxDynamicSharedMemorySize,
                             STAGES * STAGE_BYTES);
        attr_set = true;
    }

    // N tiles fastest: CTAs in a row share A panel; W (32 MB fp16) stays in L2.
    gemm_f16_kernel<<<dim3(DOUT / BN, BATCH / BM), 256, STAGES * STAGE_BYTES>>>(
        ar_ptr, wt_ptr, b_ptr, out);
}